// round 16
// baseline (speedup 1.0000x reference)
#include <cuda_runtime.h>
#include <cuda_fp16.h>

// N=50000 nodes, D=64, E=800000 edges, HID=64.
//   Pa[n][j] = emb[n] . W1[0:64 , j] + b1[j]   (stored fp16)
//   Pb[n][j] = emb[n] . W1[64:128, j]          (stored fp16)
//   out[e]   = W2 . relu(Pa[src[e]] + Pb[dst[e]]) + b2
// R16: ONE launch, spin-gated hybrid grid. Blocks [0, npre) do the precompute
//      (64-node MMA tiles) and release a monotonic counter; blocks [npre, ...)
//      are ONE-SHOT edge blocks (R13 body) that run their prologue, then spin
//      until all pre-blocks of this replay are done. Removes the ~8us
//      inter-kernel gap while keeping the one-shot edge behavior that every
//      persistent/grid-stride variant failed to match.

#define MAX_NODES 50048
#define D 64
#define HID 64

__device__ __half g_Pa[MAX_NODES * HID];   // includes b1
__device__ __half g_Pb[MAX_NODES * HID];
__device__ unsigned long long g_done = 0;  // pre-blocks completed (monotonic)
__device__ unsigned long long g_tick = 0;  // edge-block tickets   (monotonic)

__device__ __forceinline__ float edge_dot(uint4 av, uint4 bv,
                                          float4 w0, float4 w1)
{
    const __half2 z2 = __half2half2(__float2half(0.f));
    __half2 s0 = __hmax2(__hadd2(*(__half2*)&av.x, *(__half2*)&bv.x), z2);
    __half2 s1 = __hmax2(__hadd2(*(__half2*)&av.y, *(__half2*)&bv.y), z2);
    __half2 s2 = __hmax2(__hadd2(*(__half2*)&av.z, *(__half2*)&bv.z), z2);
    __half2 s3 = __hmax2(__hadd2(*(__half2*)&av.w, *(__half2*)&bv.w), z2);
    float2 f0 = __half22float2(s0);
    float2 f1 = __half22float2(s1);
    float2 f2 = __half22float2(s2);
    float2 f3 = __half22float2(s3);
    return f0.x * w0.x + f0.y * w0.y
         + f1.x * w0.z + f1.y * w0.w
         + f2.x * w1.x + f2.y * w1.y
         + f3.x * w1.z + f3.y * w1.w;
}

__global__ void __launch_bounds__(256, 5)
hybrid_kernel(const float* __restrict__ emb,
              const int*   __restrict__ ei,
              const float* __restrict__ W1,
              const float* __restrict__ b1,
              const float* __restrict__ W2,
              const float* __restrict__ b2,
              float*       __restrict__ out,
              int n_nodes, int E, int npre, int eblocks)
{
    __shared__ __align__(16) __half As[64 * 72];    // emb tile
    __shared__ __align__(16) __half Bs[128 * 72];   // W1 transposed

    const int tid  = threadIdx.x;
    const int warp = tid >> 5, lane = tid & 31;

    if ((int)blockIdx.x < npre) {
        // ================= Pre path: one 64-node tile =================
        const int node0 = (int)blockIdx.x << 6;

        // Load emb tile (64 x 64 fp32 -> fp16), coalesced float4.
        {
            int r  = tid >> 2;            // 0..63
            int c0 = (tid & 3) << 4;      // 0,16,32,48
            int gn = node0 + r;
            __half2* dst = (__half2*)&As[r * 72 + c0];
            if (gn < n_nodes) {
                const float4* src = (const float4*)(emb + (size_t)gn * D + c0);
                #pragma unroll
                for (int q = 0; q < 4; q++) {
                    float4 v = src[q];
                    dst[q * 2]     = __floats2half2_rn(v.x, v.y);
                    dst[q * 2 + 1] = __floats2half2_rn(v.z, v.w);
                }
            } else {
                #pragma unroll
                for (int q = 0; q < 8; q++) dst[q] = __half2half2(__float2half(0.f));
            }
        }
        // Load W1 transposed: Bs[o][k]; o<64 -> W1a[:,o], o>=64 -> W1b[:,o-64]
        for (int i = tid; i < 128 * 64; i += 256) {
            int k = i >> 7, o = i & 127;
            float w = W1[((o < 64) ? k : 64 + k) * HID + (o & 63)];
            Bs[o * 72 + k] = __float2half(w);
        }
        __syncthreads();

        const int g4 = lane >> 2, tig = lane & 3;
        const int mrow = (warp & 3) * 16;
        const int hb   = (warp >> 2) * 64;

        float acc[8][4];
        #pragma unroll
        for (int nt = 0; nt < 8; nt++)
            #pragma unroll
            for (int q = 0; q < 4; q++) acc[nt][q] = 0.f;

        #pragma unroll
        for (int kt = 0; kt < 4; kt++) {
            const __half* abase = &As[(mrow + g4) * 72 + kt * 16 + tig * 2];
            unsigned int a0 = *(const unsigned int*)(abase);
            unsigned int a1 = *(const unsigned int*)(abase + 8 * 72);
            unsigned int a2 = *(const unsigned int*)(abase + 8);
            unsigned int a3 = *(const unsigned int*)(abase + 8 * 72 + 8);
            #pragma unroll
            for (int nt = 0; nt < 8; nt++) {
                const __half* bbase = &Bs[(hb + nt * 8 + g4) * 72 + kt * 16 + tig * 2];
                unsigned int b0  = *(const unsigned int*)(bbase);
                unsigned int b1r = *(const unsigned int*)(bbase + 8);
                asm volatile(
                    "mma.sync.aligned.m16n8k16.row.col.f32.f16.f16.f32 "
                    "{%0,%1,%2,%3}, {%4,%5,%6,%7}, {%8,%9}, {%0,%1,%2,%3};"
                    : "+f"(acc[nt][0]), "+f"(acc[nt][1]), "+f"(acc[nt][2]), "+f"(acc[nt][3])
                    : "r"(a0), "r"(a1), "r"(a2), "r"(a3), "r"(b0), "r"(b1r));
            }
        }

        // Direct epilogue stores (scattered STG.32 - latency-absorbed).
        const int n0 = node0 + mrow + g4;
        const int n1 = n0 + 8;
        #pragma unroll
        for (int nt = 0; nt < 8; nt++) {
            int o = hb + nt * 8 + tig * 2;
            float bx = 0.f, by = 0.f;
            if (o < 64) { bx = b1[o]; by = b1[o + 1]; }
            __half* tab = (o < 64) ? g_Pa : g_Pb;
            int col = o & 63;
            if (n0 < n_nodes)
                *(__half2*)(tab + (size_t)n0 * HID + col) =
                    __floats2half2_rn(acc[nt][0] + bx, acc[nt][1] + by);
            if (n1 < n_nodes)
                *(__half2*)(tab + (size_t)n1 * HID + col) =
                    __floats2half2_rn(acc[nt][2] + bx, acc[nt][3] + by);
        }

        // Release: table writes visible before the counter bump.
        __threadfence();
        __syncthreads();
        if (tid == 0) atomicAdd(&g_done, 1ULL);
        return;
    }

    // ================= Edge path (one-shot, R13 body) =================
    const int ebid = (int)blockIdx.x - npre;
    int wg   = ebid * 8 + warp;
    int t = lane & 7;                // slot within edge group
    int g = lane >> 3;               // edge group 0..3

    // ---- Prologue: independent of the tables ----
    float4 w0 = *(const float4*)(W2 + (t << 3));
    float4 w1 = *(const float4*)(W2 + (t << 3) + 4);
    float b2v = __ldg(b2);

    int e0 = wg * 16 + g * 4;        // first of 4 consecutive edges
    int ec = e0;
    if (ec + 4 > E) ec = (E >= 4) ? (E - 4) : 0;   // clamp (recompute ok)

    int4 sv, dv;
    if (((E | ec) & 3) == 0) {       // uniform; always true for E%4==0
        sv = *(const int4*)(ei + ec);
        dv = *(const int4*)(ei + E + ec);
    } else {
        sv.x = ei[ec];     sv.y = ei[ec + 1];     sv.z = ei[ec + 2];     sv.w = ei[ec + 3];
        dv.x = ei[E + ec]; dv.y = ei[E + ec + 1]; dv.z = ei[E + ec + 2]; dv.w = ei[E + ec + 3];
    }

    // ---- Gate: wait until this replay's pre-blocks have all released ----
    if (tid == 0) {
        unsigned long long tk = atomicAdd(&g_tick, 1ULL);
        unsigned long long epoch = tk / (unsigned long long)eblocks;
        unsigned long long target = (unsigned long long)npre * (epoch + 1ULL);
        while (*(volatile unsigned long long*)&g_done < target) { }
    }
    __syncthreads();
    __threadfence();

    // 8 independent 128B gathers in flight
    uint4 A0 = ((const uint4*)(g_Pa + (size_t)sv.x * HID))[t];
    uint4 B0 = ((const uint4*)(g_Pb + (size_t)dv.x * HID))[t];
    uint4 A1 = ((const uint4*)(g_Pa + (size_t)sv.y * HID))[t];
    uint4 B1 = ((const uint4*)(g_Pb + (size_t)dv.y * HID))[t];
    uint4 A2 = ((const uint4*)(g_Pa + (size_t)sv.z * HID))[t];
    uint4 B2 = ((const uint4*)(g_Pb + (size_t)dv.z * HID))[t];
    uint4 A3 = ((const uint4*)(g_Pa + (size_t)sv.w * HID))[t];
    uint4 B3 = ((const uint4*)(g_Pb + (size_t)dv.w * HID))[t];

    float p0 = edge_dot(A0, B0, w0, w1);
    float p1 = edge_dot(A1, B1, w0, w1);
    float p2 = edge_dot(A2, B2, w0, w1);
    float p3 = edge_dot(A3, B3, w0, w1);

    #pragma unroll
    for (int m = 4; m >= 1; m >>= 1) {
        p0 += __shfl_xor_sync(0xffffffffu, p0, m);
        p1 += __shfl_xor_sync(0xffffffffu, p1, m);
        p2 += __shfl_xor_sync(0xffffffffu, p2, m);
        p3 += __shfl_xor_sync(0xffffffffu, p3, m);
    }

    if (t == 0 && ec < E) {
        if ((ec & 3) == 0 && ec + 4 <= E) {
            float4 r;
            r.x = p0 + b2v; r.y = p1 + b2v; r.z = p2 + b2v; r.w = p3 + b2v;
            *(float4*)(out + ec) = r;        // clamp duplicates identical
        } else {
            if (ec < E)     out[ec]     = p0 + b2v;
            if (ec + 1 < E) out[ec + 1] = p1 + b2v;
            if (ec + 2 < E) out[ec + 2] = p2 + b2v;
            if (ec + 3 < E) out[ec + 3] = p3 + b2v;
        }
    }
}

// ---------------------------------------------------------------------------
extern "C" void kernel_launch(void* const* d_in, const int* in_sizes, int n_in,
                              void* d_out, int out_size)
{
    const float* emb = (const float*)d_in[0];
    const int*   ei  = (const int*)d_in[1];     // int32 (JAX x64 disabled)
    const float* W1  = (const float*)d_in[2];
    const float* b1  = (const float*)d_in[3];
    const float* W2  = (const float*)d_in[4];
    const float* b2  = (const float*)d_in[5];
    float*       out = (float*)d_out;

    int n_nodes = in_sizes[0] / D;        // 50000
    int E       = in_sizes[1] / 2;        // 800000

    int npre    = (n_nodes + 63) / 64;                 // 782 pre-blocks (first)
    int eblocks = (int)(((long long)E + 127) / 128);   // 6250 one-shot edge blocks

    hybrid_kernel<<<npre + eblocks, 256>>>(emb, ei, W1, b1, W2, b2, out,
                                           n_nodes, E, npre, eblocks);
}

// round 17
// speedup vs baseline: 1.4543x; 1.4543x over previous
#include <cuda_runtime.h>
#include <cuda_fp16.h>

// N=50000 nodes, D=64, E=800000 edges, HID=64.
//   Pa[n][j] = emb[n] . W1[0:64 , j] + b1[j]   (stored fp16)
//   Pb[n][j] = emb[n] . W1[64:128, j]          (stored fp16)
//   out[e]   = W2 . relu(Pa[src[e]] + Pb[dst[e]]) + b2
// R17: R11 fused persistent kernel + two phase-2 edits:
//      (1) next-iteration index prefetch (index load off the serial chain)
//      (2) W2 re-read from smem per iteration (frees 8 persistent regs so the
//          prefetch fits the 64-reg / 4-blocks-per-SM budget).

#define MAX_NODES 50048
#define D 64
#define HID 64
#define GRID_BLOCKS 592      // 4 blocks/SM x 148 SMs -> co-resident guaranteed

__device__ __half g_Pa[MAX_NODES * HID];   // includes b1
__device__ __half g_Pb[MAX_NODES * HID];
__device__ unsigned int g_bar = 0;         // monotonic ticket counter (replay-safe)

__device__ __forceinline__ float edge_dot(uint4 av, uint4 bv,
                                          float4 w0, float4 w1)
{
    const __half2 z2 = __half2half2(__float2half(0.f));
    __half2 s0 = __hmax2(__hadd2(*(__half2*)&av.x, *(__half2*)&bv.x), z2);
    __half2 s1 = __hmax2(__hadd2(*(__half2*)&av.y, *(__half2*)&bv.y), z2);
    __half2 s2 = __hmax2(__hadd2(*(__half2*)&av.z, *(__half2*)&bv.z), z2);
    __half2 s3 = __hmax2(__hadd2(*(__half2*)&av.w, *(__half2*)&bv.w), z2);
    float2 f0 = __half22float2(s0);
    float2 f1 = __half22float2(s1);
    float2 f2 = __half22float2(s2);
    float2 f3 = __half22float2(s3);
    return f0.x * w0.x + f0.y * w0.y
         + f1.x * w0.z + f1.y * w0.w
         + f2.x * w1.x + f2.y * w1.y
         + f3.x * w1.z + f3.y * w1.w;
}

__device__ __forceinline__ void load_idx(const int* __restrict__ ei, int E,
                                         int base, int g, int4& sv, int4& dv)
{
    int ec = base + g * 4;
    if (ec + 4 > E) ec = (E >= 4) ? (E - 4) : 0;
    if (((E | ec) & 3) == 0) {
        sv = *(const int4*)(ei + ec);              // broadcast within group
        dv = *(const int4*)(ei + E + ec);
    } else {
        sv.x = ei[ec];     sv.y = ei[ec + 1];     sv.z = ei[ec + 2];     sv.w = ei[ec + 3];
        dv.x = ei[E + ec]; dv.y = ei[E + ec + 1]; dv.z = ei[E + ec + 2]; dv.w = ei[E + ec + 3];
    }
}

__global__ void __launch_bounds__(256, 4)
fused_kernel(const float* __restrict__ emb,
             const int*   __restrict__ ei,
             const float* __restrict__ W1,
             const float* __restrict__ b1,
             const float* __restrict__ W2,
             const float* __restrict__ b2,
             float*       __restrict__ out,
             int n_nodes, int E)
{
    // Phase-1 smem: As[64][72] + Bs[128][72] = 27648B; St[64][136] reuses it.
    __shared__ __align__(16) unsigned char smem_raw[27648];
    __half* As = (__half*)smem_raw;            // [64][72]
    __half* Bs = As + 64 * 72;                 // [128][72]
    __half* St = (__half*)smem_raw;            // [64][136]
    float*  sW2 = (float*)smem_raw;            // [64] (phase-2 overlay)

    const int tid  = threadIdx.x;
    const int warp = tid >> 5, lane = tid & 31;

    // ===================== Phase 1: precompute tables =====================
    const int ntiles = (n_nodes + 63) >> 6;
    for (int tile = blockIdx.x; tile < ntiles; tile += gridDim.x) {
        const int node0 = tile << 6;
        __syncthreads();   // previous iter's St reads done before overwriting

        // Load emb tile (64 x 64 fp32 -> fp16). Coalesced float4 reads.
        {
            int r  = tid >> 2;            // 0..63
            int c0 = (tid & 3) << 4;      // 0,16,32,48
            int gn = node0 + r;
            __half2* dst = (__half2*)&As[r * 72 + c0];
            if (gn < n_nodes) {
                const float4* src = (const float4*)(emb + (size_t)gn * D + c0);
                #pragma unroll
                for (int q = 0; q < 4; q++) {
                    float4 v = src[q];
                    dst[q * 2]     = __floats2half2_rn(v.x, v.y);
                    dst[q * 2 + 1] = __floats2half2_rn(v.z, v.w);
                }
            } else {
                #pragma unroll
                for (int q = 0; q < 8; q++) dst[q] = __half2half2(__float2half(0.f));
            }
        }
        // Load W1 transposed: Bs[o][k]; o<64 -> W1a[:,o], o>=64 -> W1b[:,o-64]
        for (int i = tid; i < 128 * 64; i += 256) {
            int k = i >> 7, o = i & 127;
            float w = W1[((o < 64) ? k : 64 + k) * HID + (o & 63)];
            Bs[o * 72 + k] = __float2half(w);
        }
        __syncthreads();

        // MMA: warp w -> rows mrow=(w&3)*16, out half hb=(w>>2)*64 (8 n-tiles).
        const int g4 = lane >> 2, tig = lane & 3;
        const int mrow = (warp & 3) * 16;
        const int hb   = (warp >> 2) * 64;

        float acc[8][4];
        #pragma unroll
        for (int nt = 0; nt < 8; nt++)
            #pragma unroll
            for (int q = 0; q < 4; q++) acc[nt][q] = 0.f;

        #pragma unroll
        for (int kt = 0; kt < 4; kt++) {
            const __half* abase = &As[(mrow + g4) * 72 + kt * 16 + tig * 2];
            unsigned int a0 = *(const unsigned int*)(abase);
            unsigned int a1 = *(const unsigned int*)(abase + 8 * 72);
            unsigned int a2 = *(const unsigned int*)(abase + 8);
            unsigned int a3 = *(const unsigned int*)(abase + 8 * 72 + 8);
            #pragma unroll
            for (int nt = 0; nt < 8; nt++) {
                const __half* bbase = &Bs[(hb + nt * 8 + g4) * 72 + kt * 16 + tig * 2];
                unsigned int b0  = *(const unsigned int*)(bbase);
                unsigned int b1r = *(const unsigned int*)(bbase + 8);
                asm volatile(
                    "mma.sync.aligned.m16n8k16.row.col.f32.f16.f16.f32 "
                    "{%0,%1,%2,%3}, {%4,%5,%6,%7}, {%8,%9}, {%0,%1,%2,%3};"
                    : "+f"(acc[nt][0]), "+f"(acc[nt][1]), "+f"(acc[nt][2]), "+f"(acc[nt][3])
                    : "r"(a0), "r"(a1), "r"(a2), "r"(a3), "r"(b0), "r"(b1r));
            }
        }
        __syncthreads();   // fragment LDS done; safe to overwrite with St

        // Stage rows (272B stride; STS.32 conflict-free).
        {
            const int r0 = mrow + g4;
            const int r1 = r0 + 8;
            #pragma unroll
            for (int nt = 0; nt < 8; nt++) {
                int o = hb + nt * 8 + tig * 2;
                float bx = 0.f, by = 0.f;
                if (o < 64) { bx = b1[o]; by = b1[o + 1]; }
                *(__half2*)(St + r0 * 136 + o) =
                    __floats2half2_rn(acc[nt][0] + bx, acc[nt][1] + by);
                *(__half2*)(St + r1 * 136 + o) =
                    __floats2half2_rn(acc[nt][2] + bx, acc[nt][3] + by);
            }
        }
        __syncthreads();

        // Coalesced copy out: 64 rows x 8 x 16B per table.
        for (int seg = tid; seg < 512; seg += 256) {
            int r = seg >> 3, c = seg & 7;
            int gn = node0 + r;
            if (gn < n_nodes) {
                *(uint4*)(g_Pa + (size_t)gn * HID + c * 8) =
                    *(const uint4*)(St + r * 136 + c * 8);
                *(uint4*)(g_Pb + (size_t)gn * HID + c * 8) =
                    *(const uint4*)(St + r * 136 + 64 + c * 8);
            }
        }
    }

    // ===================== Device-wide ticket barrier =====================
    __threadfence();
    __syncthreads();
    if (tid == 0) {
        unsigned int ticket = atomicAdd(&g_bar, 1u);
        unsigned int target = (ticket / gridDim.x + 1u) * gridDim.x;
        while (*(volatile unsigned int*)&g_bar < target) { }
    }
    __syncthreads();
    __threadfence();

    // ===================== Phase 2: edge MLP =====================
    // Stage W2 in smem (frees 8 persistent regs for the index prefetch).
    if (tid < 64) sW2[tid] = W2[tid];
    __syncthreads();

    const int t = lane & 7;          // slot within 8-lane edge group
    const int g = lane >> 3;         // edge group 0..3
    float b2v = __ldg(b2);

    const int nwarps = gridDim.x * (blockDim.x >> 5);
    const int wg = blockIdx.x * (blockDim.x >> 5) + warp;
    const int stride = nwarps * 16;

    int base = wg * 16;
    if (base < E) {
        int4 sv, dv;
        load_idx(ei, E, base, g, sv, dv);

        for (;;) {
            // Prefetch next iteration's indices BEFORE the gathers.
            int nb = base + stride;
            bool hn = nb < E;
            int4 nsv, ndv;
            if (hn) load_idx(ei, E, nb, g, nsv, ndv);

            // 8 independent 128B gathers in flight
            uint4 A0 = ((const uint4*)(g_Pa + (size_t)sv.x * HID))[t];
            uint4 B0 = ((const uint4*)(g_Pb + (size_t)dv.x * HID))[t];
            uint4 A1 = ((const uint4*)(g_Pa + (size_t)sv.y * HID))[t];
            uint4 B1 = ((const uint4*)(g_Pb + (size_t)dv.y * HID))[t];
            uint4 A2 = ((const uint4*)(g_Pa + (size_t)sv.z * HID))[t];
            uint4 B2 = ((const uint4*)(g_Pb + (size_t)dv.z * HID))[t];
            uint4 A3 = ((const uint4*)(g_Pa + (size_t)sv.w * HID))[t];
            uint4 B3 = ((const uint4*)(g_Pb + (size_t)dv.w * HID))[t];

            // Weights from smem (LDS latency hidden under the gathers).
            float4 w0 = *(const float4*)(sW2 + (t << 3));
            float4 w1 = *(const float4*)(sW2 + (t << 3) + 4);

            float p0 = edge_dot(A0, B0, w0, w1);
            float p1 = edge_dot(A1, B1, w0, w1);
            float p2 = edge_dot(A2, B2, w0, w1);
            float p3 = edge_dot(A3, B3, w0, w1);

            #pragma unroll
            for (int m = 4; m >= 1; m >>= 1) {
                p0 += __shfl_xor_sync(0xffffffffu, p0, m);
                p1 += __shfl_xor_sync(0xffffffffu, p1, m);
                p2 += __shfl_xor_sync(0xffffffffu, p2, m);
                p3 += __shfl_xor_sync(0xffffffffu, p3, m);
            }

            int ec = base + g * 4;
            if (ec + 4 > E) ec = (E >= 4) ? (E - 4) : 0;
            if (t == 0 && ec < E) {
                if ((ec & 3) == 0 && ec + 4 <= E) {
                    float4 r;
                    r.x = p0 + b2v; r.y = p1 + b2v; r.z = p2 + b2v; r.w = p3 + b2v;
                    *(float4*)(out + ec) = r;      // clamp duplicates identical
                } else {
                    if (ec < E)     out[ec]     = p0 + b2v;
                    if (ec + 1 < E) out[ec + 1] = p1 + b2v;
                    if (ec + 2 < E) out[ec + 2] = p2 + b2v;
                    if (ec + 3 < E) out[ec + 3] = p3 + b2v;
                }
            }

            if (!hn) break;
            base = nb; sv = nsv; dv = ndv;
        }
    }
}

// ---------------------------------------------------------------------------
extern "C" void kernel_launch(void* const* d_in, const int* in_sizes, int n_in,
                              void* d_out, int out_size)
{
    const float* emb = (const float*)d_in[0];
    const int*   ei  = (const int*)d_in[1];     // int32 (JAX x64 disabled)
    const float* W1  = (const float*)d_in[2];
    const float* b1  = (const float*)d_in[3];
    const float* W2  = (const float*)d_in[4];
    const float* b2  = (const float*)d_in[5];
    float*       out = (float*)d_out;

    int n_nodes = in_sizes[0] / D;        // 50000
    int E       = in_sizes[1] / 2;        // 800000

    fused_kernel<<<GRID_BLOCKS, 256>>>(emb, ei, W1, b1, W2, b2, out, n_nodes, E);
}